// round 1
// baseline (speedup 1.0000x reference)
#include <cuda_runtime.h>
#include <cstdint>

// Problem dims
#define BDIM 16384
#define HDIM 1024
constexpr size_t NBH = (size_t)BDIM * HDIM;

// GEMM tile config
constexpr int BM = 128, BN = 64, BK = 32;

// Scratch (static device arrays: allocation-free per harness rules)
__device__ float g_k[NBH];
__device__ float g_v[NBH];
__device__ float g_r[NBH];   // pre-sigmoid r
__device__ float g_rw[NBH];  // r * wkv

// ---------------------------------------------------------------------------
// tf32 helpers
// ---------------------------------------------------------------------------
__device__ __forceinline__ uint32_t tf32_rna(float f) {
    uint32_t u;
    asm("cvt.rna.tf32.f32 %0, %1;" : "=r"(u) : "f"(f));
    return u;
}

__device__ __forceinline__ void mma_tf32(float* c, const uint32_t* a, const uint32_t* b) {
    asm volatile(
        "mma.sync.aligned.m16n8k8.row.col.f32.tf32.tf32.f32 "
        "{%0,%1,%2,%3}, {%4,%5,%6,%7}, {%8,%9}, {%0,%1,%2,%3};"
        : "+f"(c[0]), "+f"(c[1]), "+f"(c[2]), "+f"(c[3])
        : "r"(a[0]), "r"(a[1]), "r"(a[2]), "r"(a[3]),
          "r"(b[0]), "r"(b[1]));
}

// ---------------------------------------------------------------------------
// GEMM body: D[M,N] = A[M,K] @ W[N,K]^T   (both K-contiguous, "TN")
// tf32x3 split precision: err ~1e-6 relative. BLEND fuses the token-shift mix
// into the A load: A_eff = x*mix + alpha*(1-mix), mix indexed by K column.
// ---------------------------------------------------------------------------
template <bool BLEND>
__device__ __forceinline__ void gemm_body(
    const float* __restrict__ A, const float* __restrict__ A2,
    const float* __restrict__ mix, const float* __restrict__ W,
    float* __restrict__ D)
{
    __shared__ __align__(16) float As[2][BM][BK];  // [hi/lo][row][k], XOR swizzled
    __shared__ __align__(16) float Bs[2][BN][BK];

    const int tid  = threadIdx.x;
    const int lane = tid & 31;
    const int warp = tid >> 5;
    const int wm = warp >> 1;   // 0..3
    const int wn = warp & 1;    // 0..1
    const int m0 = blockIdx.y * BM;
    const int n0 = blockIdx.x * BN;
    const int g  = lane >> 2;   // 0..7
    const int tg = lane & 3;    // 0..3
    const int sw = g << 2;      // fragment-load swizzle (row&7 == g for all frag rows)

    float acc[2][4][4];
#pragma unroll
    for (int i = 0; i < 2; i++)
#pragma unroll
        for (int j = 0; j < 4; j++)
#pragma unroll
            for (int l = 0; l < 4; l++) acc[i][j][l] = 0.f;

    for (int kt = 0; kt < HDIM; kt += BK) {
        // ---- load A tile (128x32) : 1024 float4, 4 per thread ----
#pragma unroll
        for (int it = 0; it < 4; it++) {
            int q = it * 256 + tid;
            int r = q >> 3;
            int c = (q & 7) << 2;
            int cs = c ^ ((r & 7) << 2);
            float4 xv = *(const float4*)(A + (size_t)(m0 + r) * HDIM + kt + c);
            float4 v;
            if (BLEND) {
                float4 av = *(const float4*)(A2 + (size_t)(m0 + r) * HDIM + kt + c);
                float4 mv = *(const float4*)(mix + kt + c);
                v.x = xv.x * mv.x + av.x * (1.f - mv.x);
                v.y = xv.y * mv.y + av.y * (1.f - mv.y);
                v.z = xv.z * mv.z + av.z * (1.f - mv.z);
                v.w = xv.w * mv.w + av.w * (1.f - mv.w);
            } else {
                v = xv;
            }
            float4 hi, lo;
            hi.x = __uint_as_float(tf32_rna(v.x)); lo.x = __uint_as_float(tf32_rna(v.x - hi.x));
            hi.y = __uint_as_float(tf32_rna(v.y)); lo.y = __uint_as_float(tf32_rna(v.y - hi.y));
            hi.z = __uint_as_float(tf32_rna(v.z)); lo.z = __uint_as_float(tf32_rna(v.z - hi.z));
            hi.w = __uint_as_float(tf32_rna(v.w)); lo.w = __uint_as_float(tf32_rna(v.w - hi.w));
            *(float4*)&As[0][r][cs] = hi;
            *(float4*)&As[1][r][cs] = lo;
        }
        // ---- load B tile (64x32 of W) : 512 float4, 2 per thread ----
#pragma unroll
        for (int it = 0; it < 2; it++) {
            int q = it * 256 + tid;
            int r = q >> 3;
            int c = (q & 7) << 2;
            int cs = c ^ ((r & 7) << 2);
            float4 wv = *(const float4*)(W + (size_t)(n0 + r) * HDIM + kt + c);
            float4 hi, lo;
            hi.x = __uint_as_float(tf32_rna(wv.x)); lo.x = __uint_as_float(tf32_rna(wv.x - hi.x));
            hi.y = __uint_as_float(tf32_rna(wv.y)); lo.y = __uint_as_float(tf32_rna(wv.y - hi.y));
            hi.z = __uint_as_float(tf32_rna(wv.z)); lo.z = __uint_as_float(tf32_rna(wv.z - hi.z));
            hi.w = __uint_as_float(tf32_rna(wv.w)); lo.w = __uint_as_float(tf32_rna(wv.w - hi.w));
            *(float4*)&Bs[0][r][cs] = hi;
            *(float4*)&Bs[1][r][cs] = lo;
        }
        __syncthreads();

#pragma unroll
        for (int kk = 0; kk < BK; kk += 8) {
            uint32_t ah[2][4], al[2][4], bh[4][2], bl[4][2];
            const int c0 = (kk + tg) ^ sw;
            const int c1 = (kk + tg + 4) ^ sw;
#pragma unroll
            for (int mt = 0; mt < 2; mt++) {
                int r0 = wm * 32 + mt * 16 + g;
                int r1 = r0 + 8;
                ah[mt][0] = __float_as_uint(As[0][r0][c0]);
                ah[mt][1] = __float_as_uint(As[0][r1][c0]);
                ah[mt][2] = __float_as_uint(As[0][r0][c1]);
                ah[mt][3] = __float_as_uint(As[0][r1][c1]);
                al[mt][0] = __float_as_uint(As[1][r0][c0]);
                al[mt][1] = __float_as_uint(As[1][r1][c0]);
                al[mt][2] = __float_as_uint(As[1][r0][c1]);
                al[mt][3] = __float_as_uint(As[1][r1][c1]);
            }
#pragma unroll
            for (int nt = 0; nt < 4; nt++) {
                int cc = wn * 32 + nt * 8 + g;
                bh[nt][0] = __float_as_uint(Bs[0][cc][c0]);
                bh[nt][1] = __float_as_uint(Bs[0][cc][c1]);
                bl[nt][0] = __float_as_uint(Bs[1][cc][c0]);
                bl[nt][1] = __float_as_uint(Bs[1][cc][c1]);
            }
#pragma unroll
            for (int mt = 0; mt < 2; mt++)
#pragma unroll
                for (int nt = 0; nt < 4; nt++) {
                    mma_tf32(acc[mt][nt], ah[mt], bh[nt]);  // hi*hi
                    mma_tf32(acc[mt][nt], ah[mt], bl[nt]);  // hi*lo
                    mma_tf32(acc[mt][nt], al[mt], bh[nt]);  // lo*hi
                }
        }
        __syncthreads();
    }

    // ---- epilogue ----
#pragma unroll
    for (int mt = 0; mt < 2; mt++)
#pragma unroll
        for (int nt = 0; nt < 4; nt++) {
            int row = m0 + wm * 32 + mt * 16 + g;
            int col = n0 + wn * 32 + nt * 8 + tg * 2;
            D[(size_t)row * HDIM + col]           = acc[mt][nt][0];
            D[(size_t)row * HDIM + col + 1]       = acc[mt][nt][1];
            D[(size_t)(row + 8) * HDIM + col]     = acc[mt][nt][2];
            D[(size_t)(row + 8) * HDIM + col + 1] = acc[mt][nt][3];
        }
}

// ---------------------------------------------------------------------------
// Phase 1: k / v / r GEMMs (z selects), blend fused into A load
// ---------------------------------------------------------------------------
__global__ void __launch_bounds__(256, 2) gemm3_kernel(
    const float* __restrict__ x, const float* __restrict__ alpha,
    const float* __restrict__ mk, const float* __restrict__ mv, const float* __restrict__ mr,
    const float* __restrict__ Wk, const float* __restrict__ Wv, const float* __restrict__ Wr)
{
    const float* mix;
    const float* W;
    float* D;
    if (blockIdx.z == 0)      { mix = mk; W = Wk; D = g_k; }
    else if (blockIdx.z == 1) { mix = mv; W = Wv; D = g_v; }
    else                      { mix = mr; W = Wr; D = g_r; }
    gemm_body<true>(x, alpha, mix, W, D);
}

// ---------------------------------------------------------------------------
// Phase 2: fused elementwise WKV + state update + r*wkv + output copies
// Writes: g_rw, out[x], out[next_aa], out[next_bb], out[qq2]
// ---------------------------------------------------------------------------
__global__ void __launch_bounds__(256) ew_kernel(
    const float* __restrict__ x, const float* __restrict__ aa,
    const float* __restrict__ bb, const float* __restrict__ pp,
    const float* __restrict__ td, const float* __restrict__ tf,
    float* __restrict__ out)
{
    size_t i4 = (size_t)blockIdx.x * 256 + threadIdx.x;
    size_t i = i4 * 4;
    int h = (int)(i & (HDIM - 1));

    float4 k4 = *(const float4*)(g_k + i);
    float4 v4 = *(const float4*)(g_v + i);
    float4 r4 = *(const float4*)(g_r + i);
    float4 p4 = *(const float4*)(pp + i);
    float4 a4 = *(const float4*)(aa + i);
    float4 b4 = *(const float4*)(bb + i);
    float4 x4 = *(const float4*)(x + i);
    float4 tf4 = *(const float4*)(tf + h);
    float4 td4 = *(const float4*)(td + h);

    float4 rw4, na4, nb4, q24;
    float* kk = &k4.x; float* vv = &v4.x; float* rp = &r4.x;
    float* p = &p4.x;  float* a = &a4.x;  float* b = &b4.x;
    float* tff = &tf4.x; float* tdd = &td4.x;
    float* rw = &rw4.x; float* na = &na4.x; float* nb = &nb4.x; float* q2 = &q24.x;

#pragma unroll
    for (int j = 0; j < 4; j++) {
        float ww = tff[j] + kk[j];
        float qq = fmaxf(p[j], ww);
        float e1 = expf(p[j] - qq);
        float e2 = expf(ww - qq);
        float wkv = (e1 * a[j] + e2 * vv[j]) / (e1 * b[j] + e2);
        float w2 = p[j] + tdd[j];
        float qb = fmaxf(w2, kk[j]);
        float e1b = expf(w2 - qb);
        float e2b = expf(kk[j] - qb);
        na[j] = e1b * a[j] + e2b * vv[j];
        nb[j] = e1b * b[j] + e2b;
        q2[j] = qb;
        float r = 1.f / (1.f + expf(-rp[j]));
        rw[j] = r * wkv;
    }

    *(float4*)(g_rw + i) = rw4;
    *(float4*)(out + NBH + i)     = x4;   // slot 1: x passthrough
    *(float4*)(out + 2 * NBH + i) = na4;  // slot 2: next_aa
    *(float4*)(out + 3 * NBH + i) = nb4;  // slot 3: next_bb
    *(float4*)(out + 4 * NBH + i) = q24;  // slot 4: qq2
}

// ---------------------------------------------------------------------------
// Phase 3: out = (r*wkv) @ Wo^T  -> output slot 0
// ---------------------------------------------------------------------------
__global__ void __launch_bounds__(256, 2) gemm_out_kernel(
    const float* __restrict__ Wo, float* __restrict__ out)
{
    gemm_body<false>(g_rw, nullptr, nullptr, Wo, out);
}

// ---------------------------------------------------------------------------
extern "C" void kernel_launch(void* const* d_in, const int* in_sizes, int n_in,
                              void* d_out, int out_size)
{
    const float* x     = (const float*)d_in[0];
    const float* alpha = (const float*)d_in[1];
    const float* aa    = (const float*)d_in[2];
    const float* bb    = (const float*)d_in[3];
    const float* pp    = (const float*)d_in[4];
    const float* td    = (const float*)d_in[5];
    const float* tf    = (const float*)d_in[6];
    const float* mk    = (const float*)d_in[7];
    const float* mv    = (const float*)d_in[8];
    const float* mr    = (const float*)d_in[9];
    const float* Wk    = (const float*)d_in[10];
    const float* Wv    = (const float*)d_in[11];
    const float* Wr    = (const float*)d_in[12];
    const float* Wo    = (const float*)d_in[13];
    float* out = (float*)d_out;

    dim3 g3(HDIM / BN, BDIM / BM, 3);
    gemm3_kernel<<<g3, 256>>>(x, alpha, mk, mv, mr, Wk, Wv, Wr);

    ew_kernel<<<(unsigned)(NBH / 1024), 256>>>(x, aa, bb, pp, td, tf, out);

    dim3 g1(HDIM / BN, BDIM / BM, 1);
    gemm_out_kernel<<<g1, 256>>>(Wo, out);
}

// round 3
// speedup vs baseline: 2.3605x; 2.3605x over previous
#include <cuda_runtime.h>
#include <cuda_bf16.h>
#include <cstdint>

#define BDIM 16384
#define HDIM 1024
constexpr size_t NBH = (size_t)BDIM * HDIM;
constexpr size_t NHH = (size_t)HDIM * HDIM;

// ---------------------------------------------------------------------------
// Scratch (static device arrays: allocation-free per harness rules)
// ---------------------------------------------------------------------------
__device__ float g_k[NBH];
__device__ float g_v[NBH];
__device__ float g_r[NBH];

__device__ __align__(16) __nv_bfloat16 g_xk_hi[NBH], g_xk_lo[NBH];
__device__ __align__(16) __nv_bfloat16 g_xv_hi[NBH], g_xv_lo[NBH];
__device__ __align__(16) __nv_bfloat16 g_xr_hi[NBH], g_xr_lo[NBH];
__device__ __align__(16) __nv_bfloat16 g_rw_hi[NBH], g_rw_lo[NBH];

__device__ __align__(16) __nv_bfloat16 g_wk_hi[NHH], g_wk_lo[NHH];
__device__ __align__(16) __nv_bfloat16 g_wv_hi[NHH], g_wv_lo[NHH];
__device__ __align__(16) __nv_bfloat16 g_wr_hi[NHH], g_wr_lo[NHH];
__device__ __align__(16) __nv_bfloat16 g_wo_hi[NHH], g_wo_lo[NHH];

// ---------------------------------------------------------------------------
// PTX helpers (all legal on base sm_103 target: no tcgen05)
// ---------------------------------------------------------------------------
__device__ __forceinline__ uint32_t smem_u32(const void* p) {
    uint32_t a;
    asm("{ .reg .u64 t; cvta.to.shared.u64 t, %1; cvt.u32.u64 %0, t; }" : "=r"(a) : "l"(p));
    return a;
}
__device__ __forceinline__ void cp16(uint32_t dst, const void* src) {
    asm volatile("cp.async.cg.shared.global [%0], [%1], 16;" :: "r"(dst), "l"(src) : "memory");
}
__device__ __forceinline__ void cp_commit() {
    asm volatile("cp.async.commit_group;" ::: "memory");
}
__device__ __forceinline__ void ldsm4(uint32_t* r, uint32_t addr) {
    asm volatile("ldmatrix.sync.aligned.m8n8.x4.shared.b16 {%0,%1,%2,%3}, [%4];"
                 : "=r"(r[0]), "=r"(r[1]), "=r"(r[2]), "=r"(r[3]) : "r"(addr));
}
__device__ __forceinline__ void mma_bf16(float* c, const uint32_t* a, uint32_t b0, uint32_t b1) {
    asm volatile(
        "mma.sync.aligned.m16n8k16.row.col.f32.bf16.bf16.f32 "
        "{%0,%1,%2,%3}, {%4,%5,%6,%7}, {%8,%9}, {%0,%1,%2,%3};"
        : "+f"(c[0]), "+f"(c[1]), "+f"(c[2]), "+f"(c[3])
        : "r"(a[0]), "r"(a[1]), "r"(a[2]), "r"(a[3]), "r"(b0), "r"(b1));
}

// ---------------------------------------------------------------------------
// GEMM config: CTA 128x128x32, 8 warps (4m x 2n -> warp tile 32x64), 3 stages
// ---------------------------------------------------------------------------
constexpr int BM = 128, BN = 128, BK = 32;
constexpr int NCH = HDIM / BK;              // 32
constexpr int NSTG = 3;
constexpr int PLANE_B = BM * BK * 2;        // 8192 bytes (one plane tile)
constexpr int STAGE_B = 4 * PLANE_B;        // 32768: [Ah][Al][Bh][Bl]
constexpr int SMEM_TOT = NSTG * STAGE_B;    // 98304

// swizzled 16B-chunk offset within a plane: row stride 64B, 4 chunks/row
__device__ __forceinline__ uint32_t swz_off(int row, int ch) {
    return (uint32_t)(row * 64 + ((ch ^ ((row >> 1) & 3)) << 4));
}

// ---------------------------------------------------------------------------
// bf16x3 split GEMM: D[M,N] = A[M,K] @ W[N,K]^T
// which = base + blockIdx.z: 0=k, 1=v, 2=r, 3=out
// ---------------------------------------------------------------------------
__global__ void __launch_bounds__(256, 2) gemm_mma(int base_which, float* __restrict__ outp)
{
    extern __shared__ __align__(1024) char smem[];
    const uint32_t sb = smem_u32(smem);
    const int tid = threadIdx.x;
    const int lane = tid & 31;
    const int warp = tid >> 5;
    const int wm = warp >> 1;              // 0..3
    const int wn = warp & 1;               // 0..1
    const int m0 = blockIdx.y * BM;
    const int n0 = blockIdx.x * BN;

    const int which = base_which + blockIdx.z;
    const __nv_bfloat16 *Ah, *Al, *Bh, *Bl;
    float* D;
    if (which == 0)      { Ah = g_xk_hi; Al = g_xk_lo; Bh = g_wk_hi; Bl = g_wk_lo; D = g_k; }
    else if (which == 1) { Ah = g_xv_hi; Al = g_xv_lo; Bh = g_wv_hi; Bl = g_wv_lo; D = g_v; }
    else if (which == 2) { Ah = g_xr_hi; Al = g_xr_lo; Bh = g_wr_hi; Bl = g_wr_lo; D = g_r; }
    else                 { Ah = g_rw_hi; Al = g_rw_lo; Bh = g_wo_hi; Bl = g_wo_lo; D = outp; }

    float acc[2][8][4];
#pragma unroll
    for (int i = 0; i < 2; i++)
#pragma unroll
        for (int j = 0; j < 8; j++)
#pragma unroll
            for (int l = 0; l < 4; l++) acc[i][j][l] = 0.f;

    const __nv_bfloat16* pl[4] = { Ah, Al, Bh, Bl };
    const int rb[4] = { m0, m0, n0, n0 };

    auto fill = [&](int c) {
        const uint32_t base = sb + (c % NSTG) * STAGE_B;
        const int kt = c * BK;
#pragma unroll
        for (int t = 0; t < 4; t++) {
#pragma unroll
            for (int it = 0; it < 2; it++) {
                int q = it * 256 + tid;       // 0..511
                int row = q >> 2;
                int ch = q & 3;
                const void* src = pl[t] + (size_t)(rb[t] + row) * HDIM + kt + ch * 8;
                cp16(base + t * PLANE_B + swz_off(row, ch), src);
            }
        }
        cp_commit();
    };

    // ldmatrix lane-address components
    const int lr = lane & 7;
    const int a_row_base = wm * 32 + ((lane >> 3) & 1) * 8 + lr;   // + i*16
    const int a_ch_base  = (lane >> 4);                            // + 2*kk
    const int b_row_base = wn * 64 + (lane >> 4) * 8 + lr;         // + jj*16
    const int b_ch_base  = ((lane >> 3) & 1);                      // + 2*kk

    auto compute = [&](int c) {
        const uint32_t base = sb + (c % NSTG) * STAGE_B;
#pragma unroll
        for (int kk = 0; kk < 2; kk++) {
            uint32_t A4h[2][4], A4l[2][4];
#pragma unroll
            for (int i = 0; i < 2; i++) {
                int row = a_row_base + i * 16;
                uint32_t ad = base + swz_off(row, a_ch_base + 2 * kk);
                ldsm4(A4h[i], ad);
                ldsm4(A4l[i], ad + PLANE_B);
            }
#pragma unroll
            for (int jj = 0; jj < 4; jj++) {
                int rowb = b_row_base + jj * 16;
                uint32_t bd = base + 2 * PLANE_B + swz_off(rowb, b_ch_base + 2 * kk);
                uint32_t B4h[4], B4l[4];
                ldsm4(B4h, bd);
                ldsm4(B4l, bd + PLANE_B);
#pragma unroll
                for (int i = 0; i < 2; i++) {
                    mma_bf16(acc[i][2 * jj],     A4h[i], B4h[0], B4h[1]);
                    mma_bf16(acc[i][2 * jj],     A4h[i], B4l[0], B4l[1]);
                    mma_bf16(acc[i][2 * jj],     A4l[i], B4h[0], B4h[1]);
                    mma_bf16(acc[i][2 * jj + 1], A4h[i], B4h[2], B4h[3]);
                    mma_bf16(acc[i][2 * jj + 1], A4h[i], B4l[2], B4l[3]);
                    mma_bf16(acc[i][2 * jj + 1], A4l[i], B4h[2], B4h[3]);
                }
            }
        }
    };

    // ---- 3-stage pipeline ----
    fill(0);
    fill(1);
    for (int c = 0; c < NCH; c++) {
        if (c < NCH - 1) asm volatile("cp.async.wait_group 1;" ::: "memory");
        else             asm volatile("cp.async.wait_group 0;" ::: "memory");
        __syncthreads();
        if (c + 2 < NCH) fill(c + 2);
        compute(c);
    }

    // ---- epilogue ----
#pragma unroll
    for (int i = 0; i < 2; i++) {
        int row = m0 + wm * 32 + i * 16 + (lane >> 2);
#pragma unroll
        for (int j = 0; j < 8; j++) {
            int col = n0 + wn * 64 + j * 8 + (lane & 3) * 2;
            float2 v0 = { acc[i][j][0], acc[i][j][1] };
            float2 v1 = { acc[i][j][2], acc[i][j][3] };
            *(float2*)(D + (size_t)row * HDIM + col)       = v0;
            *(float2*)(D + (size_t)(row + 8) * HDIM + col) = v1;
        }
    }
}

// ---------------------------------------------------------------------------
// prep: blend token-shift mixes, split to bf16 hi/lo planes
// ---------------------------------------------------------------------------
__device__ __forceinline__ void blend_split_store(
    const float4& xv, const float4& av, const float4& m,
    __nv_bfloat16* hip, __nv_bfloat16* lop, size_t i)
{
    float t[4];
    t[0] = xv.x * m.x + av.x * (1.f - m.x);
    t[1] = xv.y * m.y + av.y * (1.f - m.y);
    t[2] = xv.z * m.z + av.z * (1.f - m.z);
    t[3] = xv.w * m.w + av.w * (1.f - m.w);
    union { __nv_bfloat16 h[4]; uint2 u; } H, L;
#pragma unroll
    for (int j = 0; j < 4; j++) {
        H.h[j] = __float2bfloat16(t[j]);
        L.h[j] = __float2bfloat16(t[j] - __bfloat162float(H.h[j]));
    }
    *(uint2*)(hip + i) = H.u;
    *(uint2*)(lop + i) = L.u;
}

__global__ void __launch_bounds__(256) prep_act(
    const float* __restrict__ x, const float* __restrict__ alpha,
    const float* __restrict__ mk, const float* __restrict__ mv,
    const float* __restrict__ mr)
{
    size_t i = ((size_t)blockIdx.x * 256 + threadIdx.x) * 4;
    int h = (int)(i & (HDIM - 1));
    float4 xv = *(const float4*)(x + i);
    float4 av = *(const float4*)(alpha + i);
    blend_split_store(xv, av, *(const float4*)(mk + h), g_xk_hi, g_xk_lo, i);
    blend_split_store(xv, av, *(const float4*)(mv + h), g_xv_hi, g_xv_lo, i);
    blend_split_store(xv, av, *(const float4*)(mr + h), g_xr_hi, g_xr_lo, i);
}

__global__ void __launch_bounds__(256) prep_w(
    const float* __restrict__ Wk, const float* __restrict__ Wv,
    const float* __restrict__ Wr, const float* __restrict__ Wo)
{
    const float* W;
    __nv_bfloat16 *hp, *lp;
    switch (blockIdx.y) {
        case 0: W = Wk; hp = g_wk_hi; lp = g_wk_lo; break;
        case 1: W = Wv; hp = g_wv_hi; lp = g_wv_lo; break;
        case 2: W = Wr; hp = g_wr_hi; lp = g_wr_lo; break;
        default: W = Wo; hp = g_wo_hi; lp = g_wo_lo; break;
    }
    size_t i = ((size_t)blockIdx.x * 256 + threadIdx.x) * 4;
    float4 w = *(const float4*)(W + i);
    float t[4] = { w.x, w.y, w.z, w.w };
    union { __nv_bfloat16 h[4]; uint2 u; } H, L;
#pragma unroll
    for (int j = 0; j < 4; j++) {
        H.h[j] = __float2bfloat16(t[j]);
        L.h[j] = __float2bfloat16(t[j] - __bfloat162float(H.h[j]));
    }
    *(uint2*)(hp + i) = H.u;
    *(uint2*)(lp + i) = L.u;
}

// ---------------------------------------------------------------------------
// Fused elementwise WKV + state update + r*wkv (split bf16) + output copies
// ---------------------------------------------------------------------------
__global__ void __launch_bounds__(256) ew_kernel(
    const float* __restrict__ x, const float* __restrict__ aa,
    const float* __restrict__ bb, const float* __restrict__ pp,
    const float* __restrict__ td, const float* __restrict__ tf,
    float* __restrict__ out)
{
    size_t i4 = (size_t)blockIdx.x * 256 + threadIdx.x;
    size_t i = i4 * 4;
    int h = (int)(i & (HDIM - 1));

    float4 k4 = *(const float4*)(g_k + i);
    float4 v4 = *(const float4*)(g_v + i);
    float4 r4 = *(const float4*)(g_r + i);
    float4 p4 = *(const float4*)(pp + i);
    float4 a4 = *(const float4*)(aa + i);
    float4 b4 = *(const float4*)(bb + i);
    float4 x4 = *(const float4*)(x + i);
    float4 tf4 = *(const float4*)(tf + h);
    float4 td4 = *(const float4*)(td + h);

    float4 na4, nb4, q24;
    float* kk = &k4.x; float* vv = &v4.x; float* rp = &r4.x;
    float* p = &p4.x;  float* a = &a4.x;  float* b = &b4.x;
    float* tff = &tf4.x; float* tdd = &td4.x;
    float* na = &na4.x; float* nb = &nb4.x; float* q2 = &q24.x;

    union { __nv_bfloat16 hh[4]; uint2 u; } RH, RL;

#pragma unroll
    for (int j = 0; j < 4; j++) {
        float ww = tff[j] + kk[j];
        float qq = fmaxf(p[j], ww);
        float e1 = expf(p[j] - qq);
        float e2 = expf(ww - qq);
        float wkv = (e1 * a[j] + e2 * vv[j]) / (e1 * b[j] + e2);
        float w2 = p[j] + tdd[j];
        float qb = fmaxf(w2, kk[j]);
        float e1b = expf(w2 - qb);
        float e2b = expf(kk[j] - qb);
        na[j] = e1b * a[j] + e2b * vv[j];
        nb[j] = e1b * b[j] + e2b;
        q2[j] = qb;
        float r = 1.f / (1.f + expf(-rp[j]));
        float rw = r * wkv;
        RH.hh[j] = __float2bfloat16(rw);
        RL.hh[j] = __float2bfloat16(rw - __bfloat162float(RH.hh[j]));
    }

    *(uint2*)(g_rw_hi + i) = RH.u;
    *(uint2*)(g_rw_lo + i) = RL.u;
    *(float4*)(out + NBH + i)     = x4;   // slot 1: x passthrough
    *(float4*)(out + 2 * NBH + i) = na4;  // slot 2: next_aa
    *(float4*)(out + 3 * NBH + i) = nb4;  // slot 3: next_bb
    *(float4*)(out + 4 * NBH + i) = q24;  // slot 4: qq2
}

// ---------------------------------------------------------------------------
extern "C" void kernel_launch(void* const* d_in, const int* in_sizes, int n_in,
                              void* d_out, int out_size)
{
    const float* x     = (const float*)d_in[0];
    const float* alpha = (const float*)d_in[1];
    const float* aa    = (const float*)d_in[2];
    const float* bb    = (const float*)d_in[3];
    const float* pp    = (const float*)d_in[4];
    const float* td    = (const float*)d_in[5];
    const float* tf    = (const float*)d_in[6];
    const float* mk    = (const float*)d_in[7];
    const float* mv    = (const float*)d_in[8];
    const float* mr    = (const float*)d_in[9];
    const float* Wk    = (const float*)d_in[10];
    const float* Wv    = (const float*)d_in[11];
    const float* Wr    = (const float*)d_in[12];
    const float* Wo    = (const float*)d_in[13];
    float* out = (float*)d_out;

    cudaFuncSetAttribute(gemm_mma, cudaFuncAttributeMaxDynamicSharedMemorySize, SMEM_TOT);

    prep_act<<<(unsigned)(NBH / 1024), 256>>>(x, alpha, mk, mv, mr);
    prep_w<<<dim3((unsigned)(NHH / 1024), 4), 256>>>(Wk, Wv, Wr, Wo);

    dim3 g3(HDIM / BN, BDIM / BM, 3);
    gemm_mma<<<g3, 256, SMEM_TOT>>>(0, nullptr);

    ew_kernel<<<(unsigned)(NBH / 1024), 256>>>(x, aa, bb, pp, td, tf, out);

    dim3 g1(HDIM / BN, BDIM / BM, 1);
    gemm_mma<<<g1, 256, SMEM_TOT>>>(3, out);
}

// round 5
// speedup vs baseline: 5.3628x; 2.2719x over previous
#include <cuda_runtime.h>
#include <cuda_fp16.h>
#include <cstdint>

#define BDIM 16384
#define HDIM 1024
constexpr size_t NBH = (size_t)BDIM * HDIM;
constexpr size_t NHH = (size_t)HDIM * HDIM;

// ---------------------------------------------------------------------------
// Scratch (static device arrays: allocation-free per harness rules)
// ---------------------------------------------------------------------------
__device__ float g_k[NBH];
__device__ float g_v[NBH];
__device__ float g_r[NBH];

__device__ __align__(16) __half g_xk[NBH];
__device__ __align__(16) __half g_xv[NBH];
__device__ __align__(16) __half g_xr[NBH];
__device__ __align__(16) __half g_rw[NBH];

__device__ __align__(16) __half g_wk[NHH];
__device__ __align__(16) __half g_wv[NHH];
__device__ __align__(16) __half g_wr[NHH];
__device__ __align__(16) __half g_wo[NHH];

// ---------------------------------------------------------------------------
// PTX helpers (legal on base sm_103 target)
// ---------------------------------------------------------------------------
__device__ __forceinline__ uint32_t smem_u32(const void* p) {
    uint32_t a;
    asm("{ .reg .u64 t; cvta.to.shared.u64 t, %1; cvt.u32.u64 %0, t; }" : "=r"(a) : "l"(p));
    return a;
}
__device__ __forceinline__ void cp16(uint32_t dst, const void* src) {
    asm volatile("cp.async.cg.shared.global [%0], [%1], 16;" :: "r"(dst), "l"(src) : "memory");
}
__device__ __forceinline__ void cp_commit() {
    asm volatile("cp.async.commit_group;" ::: "memory");
}
__device__ __forceinline__ void ldsm4(uint32_t* r, uint32_t addr) {
    asm volatile("ldmatrix.sync.aligned.m8n8.x4.shared.b16 {%0,%1,%2,%3}, [%4];"
                 : "=r"(r[0]), "=r"(r[1]), "=r"(r[2]), "=r"(r[3]) : "r"(addr));
}
__device__ __forceinline__ void mma_f16(float* c, const uint32_t* a, uint32_t b0, uint32_t b1) {
    asm volatile(
        "mma.sync.aligned.m16n8k16.row.col.f32.f16.f16.f32 "
        "{%0,%1,%2,%3}, {%4,%5,%6,%7}, {%8,%9}, {%0,%1,%2,%3};"
        : "+f"(c[0]), "+f"(c[1]), "+f"(c[2]), "+f"(c[3])
        : "r"(a[0]), "r"(a[1]), "r"(a[2]), "r"(a[3]), "r"(b0), "r"(b1));
}

// ---------------------------------------------------------------------------
// GEMM config: CTA 128x128x64, 8 warps (4m x 2n -> warp tile 32x64), 3 stages
// ---------------------------------------------------------------------------
constexpr int BM = 128, BN = 128, BK = 64;
constexpr int NCH = HDIM / BK;              // 16
constexpr int NSTG = 3;
constexpr int PLANE_B = BM * BK * 2;        // 16384 bytes (rows of 128B)
constexpr int STAGE_B = 2 * PLANE_B;        // 32768: [A][B]
constexpr int SMEM_TOT = NSTG * STAGE_B;    // 98304

// SW128: row stride 128B (8 x 16B chunks), chunk swizzled by row&7
__device__ __forceinline__ uint32_t swz_off(int row, int ch) {
    return (uint32_t)(row * 128 + ((ch ^ (row & 7)) << 4));
}

// ---------------------------------------------------------------------------
// fp16 GEMM: D[M,N] = A[M,K] @ W[N,K]^T
// which = base + blockIdx.z: 0=k, 1=v, 2=r, 3=out
// ---------------------------------------------------------------------------
__global__ void __launch_bounds__(256, 2) gemm_mma(int base_which, float* __restrict__ outp)
{
    extern __shared__ __align__(1024) char smem[];
    const uint32_t sb = smem_u32(smem);
    const int tid = threadIdx.x;
    const int lane = tid & 31;
    const int warp = tid >> 5;
    const int wm = warp >> 1;              // 0..3
    const int wn = warp & 1;               // 0..1
    const int m0 = blockIdx.y * BM;
    const int n0 = blockIdx.x * BN;

    const int which = base_which + blockIdx.z;
    const __half *A, *B;
    float* D;
    if (which == 0)      { A = g_xk; B = g_wk; D = g_k; }
    else if (which == 1) { A = g_xv; B = g_wv; D = g_v; }
    else if (which == 2) { A = g_xr; B = g_wr; D = g_r; }
    else                 { A = g_rw; B = g_wo; D = outp; }

    float acc[2][8][4];
#pragma unroll
    for (int i = 0; i < 2; i++)
#pragma unroll
        for (int j = 0; j < 8; j++)
#pragma unroll
            for (int l = 0; l < 4; l++) acc[i][j][l] = 0.f;

    const __half* pl[2] = { A, B };
    const int rb[2] = { m0, n0 };

    auto fill = [&](int c) {
        const uint32_t base = sb + (c % NSTG) * STAGE_B;
        const int kt = c * BK;
#pragma unroll
        for (int t = 0; t < 2; t++) {
#pragma unroll
            for (int it = 0; it < 4; it++) {
                int q = it * 256 + tid;       // 0..1023
                int row = q >> 3;
                int ch = q & 7;
                const void* src = pl[t] + (size_t)(rb[t] + row) * HDIM + kt + ch * 8;
                cp16(base + t * PLANE_B + swz_off(row, ch), src);
            }
        }
        cp_commit();
    };

    // ldmatrix lane-address components (proven layout from R3)
    const int lr = lane & 7;
    const int a_row_base = wm * 32 + ((lane >> 3) & 1) * 8 + lr;   // + i*16
    const int a_ch_base  = (lane >> 4);                            // + 2*kk
    const int b_row_base = wn * 64 + (lane >> 4) * 8 + lr;         // + jj*16
    const int b_ch_base  = ((lane >> 3) & 1);                      // + 2*kk

    auto compute = [&](int c) {
        const uint32_t base = sb + (c % NSTG) * STAGE_B;
#pragma unroll
        for (int kk = 0; kk < 4; kk++) {
            uint32_t A4[2][4];
#pragma unroll
            for (int i = 0; i < 2; i++) {
                int row = a_row_base + i * 16;
                ldsm4(A4[i], base + swz_off(row, a_ch_base + 2 * kk));
            }
#pragma unroll
            for (int jj = 0; jj < 4; jj++) {
                int rowb = b_row_base + jj * 16;
                uint32_t B4[4];
                ldsm4(B4, base + PLANE_B + swz_off(rowb, b_ch_base + 2 * kk));
#pragma unroll
                for (int i = 0; i < 2; i++) {
                    mma_f16(acc[i][2 * jj],     A4[i], B4[0], B4[1]);
                    mma_f16(acc[i][2 * jj + 1], A4[i], B4[2], B4[3]);
                }
            }
        }
    };

    // ---- 3-stage pipeline ----
    fill(0);
    fill(1);
    for (int c = 0; c < NCH; c++) {
        if (c < NCH - 1) asm volatile("cp.async.wait_group 1;" ::: "memory");
        else             asm volatile("cp.async.wait_group 0;" ::: "memory");
        __syncthreads();
        if (c + 2 < NCH) fill(c + 2);
        compute(c);
    }

    // ---- epilogue ----
#pragma unroll
    for (int i = 0; i < 2; i++) {
        int row = m0 + wm * 32 + i * 16 + (lane >> 2);
#pragma unroll
        for (int j = 0; j < 8; j++) {
            int col = n0 + wn * 64 + j * 8 + (lane & 3) * 2;
            float2 v0 = { acc[i][j][0], acc[i][j][1] };
            float2 v1 = { acc[i][j][2], acc[i][j][3] };
            *(float2*)(D + (size_t)row * HDIM + col)       = v0;
            *(float2*)(D + (size_t)(row + 8) * HDIM + col) = v1;
        }
    }
}

// ---------------------------------------------------------------------------
// prep: blend token-shift mixes -> fp16 planes
// ---------------------------------------------------------------------------
__device__ __forceinline__ void blend_store(
    const float4& xv, const float4& av, const float4& m, __half* dst, size_t i)
{
    union { __half h[4]; uint2 u; } H;
    H.h[0] = __float2half_rn(xv.x * m.x + av.x * (1.f - m.x));
    H.h[1] = __float2half_rn(xv.y * m.y + av.y * (1.f - m.y));
    H.h[2] = __float2half_rn(xv.z * m.z + av.z * (1.f - m.z));
    H.h[3] = __float2half_rn(xv.w * m.w + av.w * (1.f - m.w));
    *(uint2*)(dst + i) = H.u;
}

__global__ void __launch_bounds__(256) prep_act(
    const float* __restrict__ x, const float* __restrict__ alpha,
    const float* __restrict__ mk, const float* __restrict__ mv,
    const float* __restrict__ mr)
{
    size_t i = ((size_t)blockIdx.x * 256 + threadIdx.x) * 4;
    int h = (int)(i & (HDIM - 1));
    float4 xv = *(const float4*)(x + i);
    float4 av = *(const float4*)(alpha + i);
    blend_store(xv, av, *(const float4*)(mk + h), g_xk, i);
    blend_store(xv, av, *(const float4*)(mv + h), g_xv, i);
    blend_store(xv, av, *(const float4*)(mr + h), g_xr, i);
}

__global__ void __launch_bounds__(256) prep_w(
    const float* __restrict__ Wk, const float* __restrict__ Wv,
    const float* __restrict__ Wr, const float* __restrict__ Wo)
{
    const float* W;
    __half* hp;
    switch (blockIdx.y) {
        case 0: W = Wk; hp = g_wk; break;
        case 1: W = Wv; hp = g_wv; break;
        case 2: W = Wr; hp = g_wr; break;
        default: W = Wo; hp = g_wo; break;
    }
    size_t i = ((size_t)blockIdx.x * 256 + threadIdx.x) * 4;
    float4 w = *(const float4*)(W + i);
    union { __half h[4]; uint2 u; } H;
    H.h[0] = __float2half_rn(w.x);
    H.h[1] = __float2half_rn(w.y);
    H.h[2] = __float2half_rn(w.z);
    H.h[3] = __float2half_rn(w.w);
    *(uint2*)(hp + i) = H.u;
}

// ---------------------------------------------------------------------------
// Fused elementwise WKV + state update + r*wkv (fp16) + output copies
// ---------------------------------------------------------------------------
__global__ void __launch_bounds__(256) ew_kernel(
    const float* __restrict__ x, const float* __restrict__ aa,
    const float* __restrict__ bb, const float* __restrict__ pp,
    const float* __restrict__ td, const float* __restrict__ tf,
    float* __restrict__ out)
{
    size_t i4 = (size_t)blockIdx.x * 256 + threadIdx.x;
    size_t i = i4 * 4;
    int h = (int)(i & (HDIM - 1));

    float4 k4 = *(const float4*)(g_k + i);
    float4 v4 = *(const float4*)(g_v + i);
    float4 r4 = *(const float4*)(g_r + i);
    float4 p4 = *(const float4*)(pp + i);
    float4 a4 = *(const float4*)(aa + i);
    float4 b4 = *(const float4*)(bb + i);
    float4 x4 = *(const float4*)(x + i);
    float4 tf4 = *(const float4*)(tf + h);
    float4 td4 = *(const float4*)(td + h);

    float4 na4, nb4, q24;
    float* kk = &k4.x; float* vv = &v4.x; float* rp = &r4.x;
    float* p = &p4.x;  float* a = &a4.x;  float* b = &b4.x;
    float* tff = &tf4.x; float* tdd = &td4.x;
    float* na = &na4.x; float* nb = &nb4.x; float* q2 = &q24.x;

    union { __half hh[4]; uint2 u; } RW;

#pragma unroll
    for (int j = 0; j < 4; j++) {
        float ww = tff[j] + kk[j];
        float qq = fmaxf(p[j], ww);
        float e1 = expf(p[j] - qq);
        float e2 = expf(ww - qq);
        float wkv = (e1 * a[j] + e2 * vv[j]) / (e1 * b[j] + e2);
        float w2 = p[j] + tdd[j];
        float qb = fmaxf(w2, kk[j]);
        float e1b = expf(w2 - qb);
        float e2b = expf(kk[j] - qb);
        na[j] = e1b * a[j] + e2b * vv[j];
        nb[j] = e1b * b[j] + e2b;
        q2[j] = qb;
        float r = 1.f / (1.f + expf(-rp[j]));
        RW.hh[j] = __float2half_rn(r * wkv);
    }

    *(uint2*)(g_rw + i) = RW.u;
    *(float4*)(out + NBH + i)     = x4;   // slot 1: x passthrough
    *(float4*)(out + 2 * NBH + i) = na4;  // slot 2: next_aa
    *(float4*)(out + 3 * NBH + i) = nb4;  // slot 3: next_bb
    *(float4*)(out + 4 * NBH + i) = q24;  // slot 4: qq2
}

// ---------------------------------------------------------------------------
extern "C" void kernel_launch(void* const* d_in, const int* in_sizes, int n_in,
                              void* d_out, int out_size)
{
    const float* x     = (const float*)d_in[0];
    const float* alpha = (const float*)d_in[1];
    const float* aa    = (const float*)d_in[2];
    const float* bb    = (const float*)d_in[3];
    const float* pp    = (const float*)d_in[4];
    const float* td    = (const float*)d_in[5];
    const float* tf    = (const float*)d_in[6];
    const float* mk    = (const float*)d_in[7];
    const float* mv    = (const float*)d_in[8];
    const float* mr    = (const float*)d_in[9];
    const float* Wk    = (const float*)d_in[10];
    const float* Wv    = (const float*)d_in[11];
    const float* Wr    = (const float*)d_in[12];
    const float* Wo    = (const float*)d_in[13];
    float* out = (float*)d_out;

    cudaFuncSetAttribute(gemm_mma, cudaFuncAttributeMaxDynamicSharedMemorySize, SMEM_TOT);

    prep_act<<<(unsigned)(NBH / 1024), 256>>>(x, alpha, mk, mv, mr);
    prep_w<<<dim3((unsigned)(NHH / 1024), 4), 256>>>(Wk, Wv, Wr, Wo);

    dim3 g3(HDIM / BN, BDIM / BM, 3);
    gemm_mma<<<g3, 256, SMEM_TOT>>>(0, nullptr);

    ew_kernel<<<(unsigned)(NBH / 1024), 256>>>(x, aa, bb, pp, td, tf, out);

    dim3 g1(HDIM / BN, BDIM / BM, 1);
    gemm_mma<<<g1, 256, SMEM_TOT>>>(3, out);
}